// round 14
// baseline (speedup 1.0000x reference)
#include <cuda_runtime.h>
#include <cuda_fp16.h>
#include <math.h>
#include <stdint.h>

#define MM   16384
#define DD   512
#define FF   2048
#define NITER 11
#define THRESH (1.0f - 0.01f)

// SMEM tile geometry (fp16): 128 rows x (32 data + 8 pad) halves = 80B pitch
#define AP       40
#define TILE_HB  (128 * AP * 2)          // 10240 B per matrix
#define STAGE_B  (4 * TILE_HB)           // Ah, Al, Bh, Bl = 40960 B
#define NSTAGE   2
#define DYN_SMEM (NSTAGE * STAGE_B)      // 81920 B -> 2 CTAs/SM

// Epilogue staging grid: 128 rows x 68 half2 cells (64 data + 4 pad)
#define EPI_PITCH 68
#define EPI_PART  (128 * EPI_PITCH)

// Device scratch
__device__ float  g_st[(size_t)MM * DD];       // fp32 carried state
__device__ __half g_s_hi[(size_t)MM * DD];     // compact split s
__device__ __half g_s_lo[(size_t)MM * DD];
__device__ __half g_h_hi[(size_t)MM * FF];     // compact split hidden
__device__ __half g_h_lo[(size_t)MM * FF];
__device__ __half g_w1_hi[(size_t)FF * DD];    // W1^T [F][D]
__device__ __half g_w1_lo[(size_t)FF * DD];
__device__ __half g_w2_hi[(size_t)DD * FF];    // W2^T [D][F]
__device__ __half g_w2_lo[(size_t)DD * FF];
__device__ float  g_hp[MM];
__device__ float  g_uw[MM];
__device__ int    g_idx[MM];
__device__ int    g_nact[NITER + 1];
__device__ int    g_flag[NITER + 1];

// ---------------------------------------------------------------------------
__device__ __forceinline__ void cp_async16_s(uint32_t dst, const void* src) {
    asm volatile("cp.async.cg.shared.global [%0], [%1], 16;\n" :: "r"(dst), "l"(src));
}
template<int N> __device__ __forceinline__ void cp_wait() {
    asm volatile("cp.async.wait_group %0;\n" :: "n"(N) : "memory");
}

__device__ __forceinline__ void f16_split(float v, __half& hi, __half& lo) {
    hi = __float2half_rn(v);
    lo = __float2half_rn(v - __half2float(hi));
}

__device__ __forceinline__ void ldsm_x4(uint32_t& r0, uint32_t& r1,
                                        uint32_t& r2, uint32_t& r3, uint32_t a) {
    asm volatile("ldmatrix.sync.aligned.m8n8.x4.shared.b16 {%0,%1,%2,%3}, [%4];"
                 : "=r"(r0), "=r"(r1), "=r"(r2), "=r"(r3) : "r"(a));
}

__device__ __forceinline__ void mma_f16(float4& d,
    uint32_t a0, uint32_t a1, uint32_t a2, uint32_t a3,
    uint32_t b0, uint32_t b1) {
    asm volatile(
        "mma.sync.aligned.m16n8k16.row.col.f32.f16.f16.f32 "
        "{%0,%1,%2,%3}, {%4,%5,%6,%7}, {%8,%9}, {%0,%1,%2,%3};"
        : "+f"(d.x), "+f"(d.y), "+f"(d.z), "+f"(d.w)
        : "r"(a0), "r"(a1), "r"(a2), "r"(a3), "r"(b0), "r"(b1));
}

// ---------------------------------------------------------------------------
__global__ void init_kernel(const float* __restrict__ state, float* __restrict__ out)
{
    size_t i = (size_t)blockIdx.x * blockDim.x + threadIdx.x;
    if (i < (size_t)MM * DD) {
        g_st[i] = state[i];
        out[i]  = 0.0f;
    }
    if (i < MM) {
        g_hp[i] = 0.0f;
        out[(size_t)MM * DD + i] = 0.0f;
        out[(size_t)MM * DD + MM + i] = 0.0f;
    }
    if (i <= NITER) { g_flag[i] = (i == 0) ? 1 : 0; g_nact[i] = 0; }
}

// Coalesced transpose + split: W[K][N] -> Th/Tl [N][K] via 32x32 smem tile
__global__ void wsplit_kernel(const float* __restrict__ W,
                              __half* __restrict__ Th, __half* __restrict__ Tl,
                              int K, int N)
{
    __shared__ float tile[32][33];
    const int bx = blockIdx.x;        // N / 32
    const int by = blockIdx.y;        // K / 32
    const int x = threadIdx.x;        // 0..31
    const int y = threadIdx.y;        // 0..7
    #pragma unroll
    for (int j = 0; j < 4; ++j)
        tile[y + j * 8][x] = W[(size_t)(by * 32 + y + j * 8) * N + bx * 32 + x];
    __syncthreads();
    #pragma unroll
    for (int j = 0; j < 4; ++j) {
        float v = tile[x][y + j * 8];
        __half hi, lo;
        f16_split(v, hi, lo);
        size_t o = (size_t)(bx * 32 + y + j * 8) * K + by * 32 + x;
        Th[o] = hi;
        Tl[o] = lo;
    }
}

// ---------------------------------------------------------------------------
// Fused ponder + prep (bit-identical halting math; loads hoisted for MLP)
// ---------------------------------------------------------------------------
__global__ void ponder_kernel(const float* __restrict__ step_emb,
                              const float* __restrict__ Wp,
                              const float* __restrict__ bp,
                              float* __restrict__ out_nup,
                              float* __restrict__ out_rem,
                              int t)
{
    if (!g_flag[t]) return;
    int row  = blockIdx.x * 8 + (threadIdx.x >> 5);
    int lane = threadIdx.x & 31;

    __shared__ int s_active;
    if (threadIdx.x == 0) s_active = 0;
    __syncthreads();

    float hp = g_hp[row];
    if (hp < 1.0f) {
        const float4* st4 = (const float4*)(g_st + (size_t)row * DD);
        const float4* e4  = (const float4*)(step_emb + (size_t)t * DD);
        const float4* w4  = (const float4*)Wp;

        // Hoist all 12 loads before the arithmetic chain (max MLP)
        float4 sld[4], eld[4], wld[4];
        #pragma unroll
        for (int j = 0; j < 4; ++j) {
            int i = lane + j * 32;
            sld[j] = st4[i];
            eld[j] = e4[i];
            wld[j] = w4[i];
        }

        float4 sv[4];
        float dot = 0.0f;
        #pragma unroll
        for (int j = 0; j < 4; ++j) {
            sv[j].x = sld[j].x + eld[j].x; sv[j].y = sld[j].y + eld[j].y;
            sv[j].z = sld[j].z + eld[j].z; sv[j].w = sld[j].w + eld[j].w;
            dot += sv[j].x * wld[j].x + sv[j].y * wld[j].y
                 + sv[j].z * wld[j].z + sv[j].w * wld[j].w;
        }
        #pragma unroll
        for (int o = 16; o; o >>= 1) dot += __shfl_xor_sync(0xffffffffu, dot, o);

        int pos = 0;
        if (lane == 0) {
            float p = 1.0f / (1.0f + expf(-(dot + bp[0])));
            float q  = hp + p;
            float nh = (q >  THRESH) ? 1.0f : 0.0f;
            float st = (q <= THRESH) ? 1.0f : 0.0f;
            hp = hp + p * st;
            float rem = out_rem[row] + nh * (1.0f - hp);
            hp = hp + nh * rem;
            out_nup[row] += 1.0f;
            g_hp[row]    = hp;
            out_rem[row] = rem;
            g_uw[row]    = p * st + nh * rem;
            pos = atomicAdd(&g_nact[t], 1);
            g_idx[pos] = row;
            if (hp < 1.0f) atomicOr(&s_active, 1);
        }
        pos = __shfl_sync(0xffffffffu, pos, 0);

        __half2* ph = (__half2*)(g_s_hi + (size_t)pos * DD);
        __half2* pl = (__half2*)(g_s_lo + (size_t)pos * DD);
        #pragma unroll
        for (int j = 0; j < 4; ++j) {
            int c2 = (lane + j * 32) * 2;
            __half h0, l0, h1, l1, h2, l2, h3, l3;
            f16_split(sv[j].x, h0, l0);
            f16_split(sv[j].y, h1, l1);
            f16_split(sv[j].z, h2, l2);
            f16_split(sv[j].w, h3, l3);
            ph[c2]     = __halves2half2(h0, h1);
            ph[c2 + 1] = __halves2half2(h2, h3);
            pl[c2]     = __halves2half2(l0, l1);
            pl[c2 + 1] = __halves2half2(l2, l3);
        }
    }
    __syncthreads();
    if (threadIdx.x == 0 && s_active) atomicOr(&g_flag[t + 1], 1);
}

// ---------------------------------------------------------------------------
// HMMA fp16-split GEMM: 128x128 CTA, 8 warps x 64x32 warp tiles, BK=32,
// 2-stage cp.async, 2 CTAs/SM. (Champion configuration, per-tile grid.)
// MODE 0: g_h = relu(g_s @ W1' + b1); smem-staged coalesced epilogue
// MODE 1: h = g_h @ W2' + b2 (masked); out_prev[row]+=h*uw; g_st[row]=h
// ---------------------------------------------------------------------------
template<int KDIM, int NDIM, int MODE>
__global__ __launch_bounds__(256, 2) void gemm_hmma(
    const float* __restrict__ bias,
    const float* __restrict__ mask,
    float* __restrict__ out_prev, int t)
{
    const int nact = g_nact[t];
    const int bm = blockIdx.y * 128;
    if (bm >= nact) return;
    const int bn = blockIdx.x * 128;

    extern __shared__ unsigned char smem_raw[];
    uint32_t sb;
    asm("{ .reg .u64 tt; cvta.to.shared.u64 tt, %1; cvt.u32.u64 %0, tt; }"
        : "=r"(sb) : "l"(smem_raw));

    const int tid = threadIdx.x;

    // ---- loader: 4 groups of 64 threads (Ah, Al, Bh, Bl), 8 chunks each ----
    const __half* Ahg = ((MODE == 0) ? g_s_hi : g_h_hi) + (size_t)bm * KDIM;
    const __half* Alg = ((MODE == 0) ? g_s_lo : g_h_lo) + (size_t)bm * KDIM;
    const __half* Bhg = ((MODE == 0) ? g_w1_hi : g_w2_hi) + (size_t)bn * KDIM;
    const __half* Blg = ((MODE == 0) ? g_w1_lo : g_w2_lo) + (size_t)bn * KDIM;
    const int tl = tid >> 6;
    const __half* tp = (tl == 0) ? Ahg : (tl == 1) ? Alg : (tl == 2) ? Bhg : Blg;
    const int u = tid & 63;
    const uint32_t tile_off = (uint32_t)tl * TILE_HB;

    #define LOAD_STAGE(slot, k0)                                               \
        do {                                                                   \
            uint32_t dst_ = sb + (uint32_t)(slot) * STAGE_B + tile_off;        \
            _Pragma("unroll")                                                  \
            for (int j_ = 0; j_ < 8; ++j_) {                                   \
                int ch_ = u + j_ * 64;                                         \
                int row_ = ch_ >> 2, c_ = ch_ & 3;                             \
                cp_async16_s(dst_ + (uint32_t)(row_ * (AP * 2) + c_ * 16),     \
                             tp + (size_t)row_ * KDIM + (k0) + c_ * 8);        \
            }                                                                  \
            asm volatile("cp.async.commit_group;" ::: "memory");               \
        } while (0)

    constexpr int KT = KDIM / 32;
    LOAD_STAGE(0, 0);
    cp_wait<0>();
    __syncthreads();

    // ---- warp tiling: 8 warps, 64x32 each (2x4 warp grid) ----
    const int lane = tid & 31;
    const int w    = tid >> 5;
    const int wm   = (w >> 2) * 64;
    const int wn   = (w & 3) * 32;
    const int lr   = lane & 15;
    const int lc   = (lane >> 4) * 8;

    float4 acc[4][4];
    #pragma unroll
    for (int i = 0; i < 4; ++i)
        #pragma unroll
        for (int j = 0; j < 4; ++j)
            acc[i][j] = make_float4(0.f, 0.f, 0.f, 0.f);

    #pragma unroll 1
    for (int kt = 0; kt < KT; ++kt) {
        if (kt + 1 < KT) LOAD_STAGE((kt + 1) & 1, (kt + 1) * 32);
        const uint32_t stg = sb + (uint32_t)(kt & 1) * STAGE_B;

        #pragma unroll
        for (int sub = 0; sub < 2; ++sub) {
            const int k0 = sub * 16;
            uint32_t bh[4][2], bl[4][2];
            #pragma unroll
            for (int njp = 0; njp < 2; ++njp) {
                uint32_t addr = stg + 2 * TILE_HB
                    + (uint32_t)(((wn + njp * 16 + lr) * AP + k0 + lc) * 2);
                uint32_t r0, r1, r2, r3;
                ldsm_x4(r0, r1, r2, r3, addr);
                bh[njp * 2][0] = r0; bh[njp * 2][1] = r2;
                bh[njp * 2 + 1][0] = r1; bh[njp * 2 + 1][1] = r3;
                addr += TILE_HB;
                ldsm_x4(r0, r1, r2, r3, addr);
                bl[njp * 2][0] = r0; bl[njp * 2][1] = r2;
                bl[njp * 2 + 1][0] = r1; bl[njp * 2 + 1][1] = r3;
            }
            #pragma unroll
            for (int mi = 0; mi < 4; ++mi) {
                uint32_t addr = stg
                    + (uint32_t)(((wm + mi * 16 + lr) * AP + k0 + lc) * 2);
                uint32_t ah0, ah1, ah2, ah3, al0, al1, al2, al3;
                ldsm_x4(ah0, ah1, ah2, ah3, addr);
                ldsm_x4(al0, al1, al2, al3, addr + TILE_HB);
                #pragma unroll
                for (int nj = 0; nj < 4; ++nj) {
                    mma_f16(acc[mi][nj], ah0, ah1, ah2, ah3, bh[nj][0], bh[nj][1]);
                    mma_f16(acc[mi][nj], ah0, ah1, ah2, ah3, bl[nj][0], bl[nj][1]);
                    mma_f16(acc[mi][nj], al0, al1, al2, al3, bh[nj][0], bh[nj][1]);
                }
            }
        }

        if (kt + 1 < KT) {
            cp_wait<0>();
            __syncthreads();
        }
    }
    #undef LOAD_STAGE

    const int g = lane >> 2;
    const int q = lane & 3;

    if (MODE == 0) {
        // ---- staged epilogue: acc -> smem (hi part0, lo part1) -> coalesced ----
        __syncthreads();                      // all warps done reading stages
        __half2* stage = (__half2*)smem_raw;  // [2][128][EPI_PITCH]
        #pragma unroll
        for (int mi = 0; mi < 4; ++mi) {
            #pragma unroll
            for (int half = 0; half < 2; ++half) {
                const int mloc = wm + mi * 16 + g + half * 8;
                #pragma unroll
                for (int nj = 0; nj < 4; ++nj) {
                    const int col = wn + nj * 8 + 2 * q;       // 0..126 even
                    float v0 = half ? acc[mi][nj].z : acc[mi][nj].x;
                    float v1 = half ? acc[mi][nj].w : acc[mi][nj].y;
                    v0 = fmaxf(v0 + bias[bn + col], 0.0f);
                    v1 = fmaxf(v1 + bias[bn + col + 1], 0.0f);
                    __half h0, l0, h1, l1;
                    f16_split(v0, h0, l0);
                    f16_split(v1, h1, l1);
                    const int cell = mloc * EPI_PITCH + (col >> 1);
                    stage[cell]            = __halves2half2(h0, h1);
                    stage[EPI_PART + cell] = __halves2half2(l0, l1);
                }
            }
        }
        __syncthreads();
        // coalesced output: each row = 64 half2 = 16 uint4; 128 rows x 16 = 2048
        #pragma unroll
        for (int it = 0; it < 8; ++it) {
            int idx = tid + it * 256;
            int rw = idx >> 4, cu = idx & 15;
            int m = bm + rw;
            if (m >= nact) continue;
            const uint4* shi = (const uint4*)(stage + rw * EPI_PITCH);
            const uint4* slo = (const uint4*)(stage + EPI_PART + rw * EPI_PITCH);
            *(uint4*)(g_h_hi + (size_t)m * NDIM + bn + cu * 8) = shi[cu];
            *(uint4*)(g_h_lo + (size_t)m * NDIM + bn + cu * 8) = slo[cu];
        }
    } else {
        #pragma unroll
        for (int mi = 0; mi < 4; ++mi) {
            #pragma unroll
            for (int half = 0; half < 2; ++half) {
                const int m = bm + wm + mi * 16 + g + half * 8;
                if (m >= nact) continue;
                const int row = g_idx[m];
                const float mk  = mask[row];
                const float uwv = g_uw[row];
                #pragma unroll
                for (int nj = 0; nj < 4; ++nj) {
                    const int col = bn + wn + nj * 8 + 2 * q;
                    float v0 = half ? acc[mi][nj].z : acc[mi][nj].x;
                    float v1 = half ? acc[mi][nj].w : acc[mi][nj].y;
                    float h0 = (v0 + bias[col])     * mk;
                    float h1 = (v1 + bias[col + 1]) * mk;
                    float* pp = out_prev + (size_t)row * NDIM + col;
                    float* sp = g_st     + (size_t)row * NDIM + col;
                    float2 pv = *(const float2*)pp;
                    pv.x += h0 * uwv;
                    pv.y += h1 * uwv;
                    *(float2*)pp = pv;
                    *(float2*)sp = make_float2(h0, h1);
                }
            }
        }
    }
}

// ---------------------------------------------------------------------------
extern "C" void kernel_launch(void* const* d_in, const int* in_sizes, int n_in,
                              void* d_out, int out_size)
{
    const float* state    = (const float*)d_in[0];
    const float* mask     = (const float*)d_in[1];
    const float* step_emb = (const float*)d_in[2];
    const float* Wp       = (const float*)d_in[3];
    const float* bp       = (const float*)d_in[4];
    const float* W1       = (const float*)d_in[5];
    const float* b1       = (const float*)d_in[6];
    const float* W2       = (const float*)d_in[7];
    const float* b2       = (const float*)d_in[8];

    float* out     = (float*)d_out;
    float* out_nup = out + (size_t)MM * DD;
    float* out_rem = out_nup + MM;

    cudaFuncSetAttribute(gemm_hmma<DD, FF, 0>,
        cudaFuncAttributeMaxDynamicSharedMemorySize, DYN_SMEM);
    cudaFuncSetAttribute(gemm_hmma<FF, DD, 1>,
        cudaFuncAttributeMaxDynamicSharedMemorySize, DYN_SMEM);

    // wsplit first (independent of init) so ncu -s 5 captures gemm2(0):
    // launches: 0 wsplit, 1 wsplit, 2 init, 3 ponder(0), 4 gemm1(0), 5 gemm2(0)
    {
        __half *w1h, *w1l, *w2h, *w2l;
        cudaGetSymbolAddress((void**)&w1h, g_w1_hi);
        cudaGetSymbolAddress((void**)&w1l, g_w1_lo);
        cudaGetSymbolAddress((void**)&w2h, g_w2_hi);
        cudaGetSymbolAddress((void**)&w2l, g_w2_lo);
        dim3 tb(32, 8);
        wsplit_kernel<<<dim3(FF / 32, DD / 32), tb>>>(W1, w1h, w1l, DD, FF);
        wsplit_kernel<<<dim3(DD / 32, FF / 32), tb>>>(W2, w2h, w2l, FF, DD);
    }

    init_kernel<<<(MM * DD + 255) / 256, 256>>>(state, out);

    dim3 g1(FF / 128, MM / 128);   // (16, 128)
    dim3 g2(DD / 128, MM / 128);   // (4, 128)

    for (int t = 0; t < NITER; ++t) {
        ponder_kernel<<<MM / 8, 256>>>(step_emb, Wp, bp, out_nup, out_rem, t);
        gemm_hmma<DD, FF, 0><<<g1, 256, DYN_SMEM>>>(b1, nullptr, nullptr, t);
        gemm_hmma<FF, DD, 1><<<g2, 256, DYN_SMEM>>>(b2, mask, out, t);
    }
}

// round 15
// speedup vs baseline: 1.0047x; 1.0047x over previous
#include <cuda_runtime.h>
#include <cuda_fp16.h>
#include <math.h>
#include <stdint.h>

#define MM   16384
#define DD   512
#define FF   2048
#define NITER 11
#define THRESH (1.0f - 0.01f)

// SMEM tile geometry (fp16): 128 rows x (32 data + 8 pad) halves = 80B pitch
#define AP       40
#define TILE_HB  (128 * AP * 2)          // 10240 B per matrix
#define STAGE_B  (4 * TILE_HB)           // Ah, Al, Bh, Bl = 40960 B
#define NSTAGE   2
#define DYN_SMEM (NSTAGE * STAGE_B)      // 81920 B -> 2 CTAs/SM

// Epilogue staging grid: 128 rows x 68 half2 cells (64 data + 4 pad)
#define EPI_PITCH 68
#define EPI_PART  (128 * EPI_PITCH)

// Device scratch
__device__ float  g_st[(size_t)MM * DD];       // fp32 carried state
__device__ __half g_s_hi[(size_t)MM * DD];     // compact split s
__device__ __half g_s_lo[(size_t)MM * DD];
__device__ __half g_h_hi[(size_t)MM * FF];     // compact split hidden
__device__ __half g_h_lo[(size_t)MM * FF];
__device__ __half g_w1_hi[(size_t)FF * DD];    // W1^T [F][D]
__device__ __half g_w1_lo[(size_t)FF * DD];
__device__ __half g_w2_hi[(size_t)DD * FF];    // W2^T [D][F]
__device__ __half g_w2_lo[(size_t)DD * FF];
__device__ float  g_hp[MM];
__device__ float  g_uw[MM];
__device__ int    g_idx[MM];
__device__ int    g_nact[NITER + 1];
__device__ int    g_flag[NITER + 1];

// ---------------------------------------------------------------------------
__device__ __forceinline__ void cp_async16_s(uint32_t dst, const void* src) {
    asm volatile("cp.async.cg.shared.global [%0], [%1], 16;\n" :: "r"(dst), "l"(src));
}
template<int N> __device__ __forceinline__ void cp_wait() {
    asm volatile("cp.async.wait_group %0;\n" :: "n"(N) : "memory");
}

__device__ __forceinline__ void f16_split(float v, __half& hi, __half& lo) {
    hi = __float2half_rn(v);
    lo = __float2half_rn(v - __half2float(hi));
}

__device__ __forceinline__ void ldsm_x4(uint32_t& r0, uint32_t& r1,
                                        uint32_t& r2, uint32_t& r3, uint32_t a) {
    asm volatile("ldmatrix.sync.aligned.m8n8.x4.shared.b16 {%0,%1,%2,%3}, [%4];"
                 : "=r"(r0), "=r"(r1), "=r"(r2), "=r"(r3) : "r"(a));
}

__device__ __forceinline__ void mma_f16(float4& d,
    uint32_t a0, uint32_t a1, uint32_t a2, uint32_t a3,
    uint32_t b0, uint32_t b1) {
    asm volatile(
        "mma.sync.aligned.m16n8k16.row.col.f32.f16.f16.f32 "
        "{%0,%1,%2,%3}, {%4,%5,%6,%7}, {%8,%9}, {%0,%1,%2,%3};"
        : "+f"(d.x), "+f"(d.y), "+f"(d.z), "+f"(d.w)
        : "r"(a0), "r"(a1), "r"(a2), "r"(a3), "r"(b0), "r"(b1));
}

// ---------------------------------------------------------------------------
// Small init: hp + flags only (g_st copied by memcpyAsync, out by memsetAsync)
// ---------------------------------------------------------------------------
__global__ void init_small_kernel()
{
    int i = blockIdx.x * blockDim.x + threadIdx.x;
    if (i < MM) g_hp[i] = 0.0f;
    if (i <= NITER) { g_flag[i] = (i == 0) ? 1 : 0; g_nact[i] = 0; }
}

// Coalesced transpose + split: W[K][N] -> Th/Tl [N][K] via 32x32 smem tile
__global__ void wsplit_kernel(const float* __restrict__ W,
                              __half* __restrict__ Th, __half* __restrict__ Tl,
                              int K, int N)
{
    __shared__ float tile[32][33];
    const int bx = blockIdx.x;        // N / 32
    const int by = blockIdx.y;        // K / 32
    const int x = threadIdx.x;        // 0..31
    const int y = threadIdx.y;        // 0..7
    #pragma unroll
    for (int j = 0; j < 4; ++j)
        tile[y + j * 8][x] = W[(size_t)(by * 32 + y + j * 8) * N + bx * 32 + x];
    __syncthreads();
    #pragma unroll
    for (int j = 0; j < 4; ++j) {
        float v = tile[x][y + j * 8];
        __half hi, lo;
        f16_split(v, hi, lo);
        size_t o = (size_t)(bx * 32 + y + j * 8) * K + by * 32 + x;
        Th[o] = hi;
        Tl[o] = lo;
    }
}

// ---------------------------------------------------------------------------
// Fused ponder + prep (bit-identical halting math; loads hoisted for MLP)
// ---------------------------------------------------------------------------
__global__ void ponder_kernel(const float* __restrict__ step_emb,
                              const float* __restrict__ Wp,
                              const float* __restrict__ bp,
                              float* __restrict__ out_nup,
                              float* __restrict__ out_rem,
                              int t)
{
    if (!g_flag[t]) return;
    int row  = blockIdx.x * 8 + (threadIdx.x >> 5);
    int lane = threadIdx.x & 31;

    __shared__ int s_active;
    if (threadIdx.x == 0) s_active = 0;
    __syncthreads();

    float hp = g_hp[row];
    if (hp < 1.0f) {
        const float4* st4 = (const float4*)(g_st + (size_t)row * DD);
        const float4* e4  = (const float4*)(step_emb + (size_t)t * DD);
        const float4* w4  = (const float4*)Wp;

        // Hoist all 12 loads before the arithmetic chain (max MLP)
        float4 sld[4], eld[4], wld[4];
        #pragma unroll
        for (int j = 0; j < 4; ++j) {
            int i = lane + j * 32;
            sld[j] = st4[i];
            eld[j] = e4[i];
            wld[j] = w4[i];
        }

        float4 sv[4];
        float dot = 0.0f;
        #pragma unroll
        for (int j = 0; j < 4; ++j) {
            sv[j].x = sld[j].x + eld[j].x; sv[j].y = sld[j].y + eld[j].y;
            sv[j].z = sld[j].z + eld[j].z; sv[j].w = sld[j].w + eld[j].w;
            dot += sv[j].x * wld[j].x + sv[j].y * wld[j].y
                 + sv[j].z * wld[j].z + sv[j].w * wld[j].w;
        }
        #pragma unroll
        for (int o = 16; o; o >>= 1) dot += __shfl_xor_sync(0xffffffffu, dot, o);

        int pos = 0;
        if (lane == 0) {
            float p = 1.0f / (1.0f + expf(-(dot + bp[0])));
            float q  = hp + p;
            float nh = (q >  THRESH) ? 1.0f : 0.0f;
            float st = (q <= THRESH) ? 1.0f : 0.0f;
            hp = hp + p * st;
            float rem = out_rem[row] + nh * (1.0f - hp);
            hp = hp + nh * rem;
            out_nup[row] += 1.0f;
            g_hp[row]    = hp;
            out_rem[row] = rem;
            g_uw[row]    = p * st + nh * rem;
            pos = atomicAdd(&g_nact[t], 1);
            g_idx[pos] = row;
            if (hp < 1.0f) atomicOr(&s_active, 1);
        }
        pos = __shfl_sync(0xffffffffu, pos, 0);

        __half2* ph = (__half2*)(g_s_hi + (size_t)pos * DD);
        __half2* pl = (__half2*)(g_s_lo + (size_t)pos * DD);
        #pragma unroll
        for (int j = 0; j < 4; ++j) {
            int c2 = (lane + j * 32) * 2;
            __half h0, l0, h1, l1, h2, l2, h3, l3;
            f16_split(sv[j].x, h0, l0);
            f16_split(sv[j].y, h1, l1);
            f16_split(sv[j].z, h2, l2);
            f16_split(sv[j].w, h3, l3);
            ph[c2]     = __halves2half2(h0, h1);
            ph[c2 + 1] = __halves2half2(h2, h3);
            pl[c2]     = __halves2half2(l0, l1);
            pl[c2 + 1] = __halves2half2(l2, l3);
        }
    }
    __syncthreads();
    if (threadIdx.x == 0 && s_active) atomicOr(&g_flag[t + 1], 1);
}

// ---------------------------------------------------------------------------
// HMMA fp16-split GEMM: 128x128 CTA, 8 warps x 64x32 warp tiles, BK=32,
// 2-stage cp.async, 2 CTAs/SM. (Champion configuration, per-tile grid.)
// MODE 0: g_h = relu(g_s @ W1' + b1); smem-staged coalesced epilogue
// MODE 1: h = g_h @ W2' + b2 (masked); out_prev[row]+=h*uw; g_st[row]=h
// ---------------------------------------------------------------------------
template<int KDIM, int NDIM, int MODE>
__global__ __launch_bounds__(256, 2) void gemm_hmma(
    const float* __restrict__ bias,
    const float* __restrict__ mask,
    float* __restrict__ out_prev, int t)
{
    const int nact = g_nact[t];
    const int bm = blockIdx.y * 128;
    if (bm >= nact) return;
    const int bn = blockIdx.x * 128;

    extern __shared__ unsigned char smem_raw[];
    uint32_t sb;
    asm("{ .reg .u64 tt; cvta.to.shared.u64 tt, %1; cvt.u32.u64 %0, tt; }"
        : "=r"(sb) : "l"(smem_raw));

    const int tid = threadIdx.x;

    // ---- loader: 4 groups of 64 threads (Ah, Al, Bh, Bl), 8 chunks each ----
    const __half* Ahg = ((MODE == 0) ? g_s_hi : g_h_hi) + (size_t)bm * KDIM;
    const __half* Alg = ((MODE == 0) ? g_s_lo : g_h_lo) + (size_t)bm * KDIM;
    const __half* Bhg = ((MODE == 0) ? g_w1_hi : g_w2_hi) + (size_t)bn * KDIM;
    const __half* Blg = ((MODE == 0) ? g_w1_lo : g_w2_lo) + (size_t)bn * KDIM;
    const int tl = tid >> 6;
    const __half* tp = (tl == 0) ? Ahg : (tl == 1) ? Alg : (tl == 2) ? Bhg : Blg;
    const int u = tid & 63;
    const uint32_t tile_off = (uint32_t)tl * TILE_HB;

    #define LOAD_STAGE(slot, k0)                                               \
        do {                                                                   \
            uint32_t dst_ = sb + (uint32_t)(slot) * STAGE_B + tile_off;        \
            _Pragma("unroll")                                                  \
            for (int j_ = 0; j_ < 8; ++j_) {                                   \
                int ch_ = u + j_ * 64;                                         \
                int row_ = ch_ >> 2, c_ = ch_ & 3;                             \
                cp_async16_s(dst_ + (uint32_t)(row_ * (AP * 2) + c_ * 16),     \
                             tp + (size_t)row_ * KDIM + (k0) + c_ * 8);        \
            }                                                                  \
            asm volatile("cp.async.commit_group;" ::: "memory");               \
        } while (0)

    constexpr int KT = KDIM / 32;
    LOAD_STAGE(0, 0);
    cp_wait<0>();
    __syncthreads();

    // ---- warp tiling: 8 warps, 64x32 each (2x4 warp grid) ----
    const int lane = tid & 31;
    const int w    = tid >> 5;
    const int wm   = (w >> 2) * 64;
    const int wn   = (w & 3) * 32;
    const int lr   = lane & 15;
    const int lc   = (lane >> 4) * 8;

    float4 acc[4][4];
    #pragma unroll
    for (int i = 0; i < 4; ++i)
        #pragma unroll
        for (int j = 0; j < 4; ++j)
            acc[i][j] = make_float4(0.f, 0.f, 0.f, 0.f);

    #pragma unroll 1
    for (int kt = 0; kt < KT; ++kt) {
        if (kt + 1 < KT) LOAD_STAGE((kt + 1) & 1, (kt + 1) * 32);
        const uint32_t stg = sb + (uint32_t)(kt & 1) * STAGE_B;

        #pragma unroll
        for (int sub = 0; sub < 2; ++sub) {
            const int k0 = sub * 16;
            uint32_t bh[4][2], bl[4][2];
            #pragma unroll
            for (int njp = 0; njp < 2; ++njp) {
                uint32_t addr = stg + 2 * TILE_HB
                    + (uint32_t)(((wn + njp * 16 + lr) * AP + k0 + lc) * 2);
                uint32_t r0, r1, r2, r3;
                ldsm_x4(r0, r1, r2, r3, addr);
                bh[njp * 2][0] = r0; bh[njp * 2][1] = r2;
                bh[njp * 2 + 1][0] = r1; bh[njp * 2 + 1][1] = r3;
                addr += TILE_HB;
                ldsm_x4(r0, r1, r2, r3, addr);
                bl[njp * 2][0] = r0; bl[njp * 2][1] = r2;
                bl[njp * 2 + 1][0] = r1; bl[njp * 2 + 1][1] = r3;
            }
            #pragma unroll
            for (int mi = 0; mi < 4; ++mi) {
                uint32_t addr = stg
                    + (uint32_t)(((wm + mi * 16 + lr) * AP + k0 + lc) * 2);
                uint32_t ah0, ah1, ah2, ah3, al0, al1, al2, al3;
                ldsm_x4(ah0, ah1, ah2, ah3, addr);
                ldsm_x4(al0, al1, al2, al3, addr + TILE_HB);
                #pragma unroll
                for (int nj = 0; nj < 4; ++nj) {
                    mma_f16(acc[mi][nj], ah0, ah1, ah2, ah3, bh[nj][0], bh[nj][1]);
                    mma_f16(acc[mi][nj], ah0, ah1, ah2, ah3, bl[nj][0], bl[nj][1]);
                    mma_f16(acc[mi][nj], al0, al1, al2, al3, bh[nj][0], bh[nj][1]);
                }
            }
        }

        if (kt + 1 < KT) {
            cp_wait<0>();
            __syncthreads();
        }
    }
    #undef LOAD_STAGE

    const int g = lane >> 2;
    const int q = lane & 3;

    if (MODE == 0) {
        // ---- staged epilogue: acc -> smem (hi part0, lo part1) -> coalesced ----
        __syncthreads();                      // all warps done reading stages
        __half2* stage = (__half2*)smem_raw;  // [2][128][EPI_PITCH]
        #pragma unroll
        for (int mi = 0; mi < 4; ++mi) {
            #pragma unroll
            for (int half = 0; half < 2; ++half) {
                const int mloc = wm + mi * 16 + g + half * 8;
                #pragma unroll
                for (int nj = 0; nj < 4; ++nj) {
                    const int col = wn + nj * 8 + 2 * q;       // 0..126 even
                    float v0 = half ? acc[mi][nj].z : acc[mi][nj].x;
                    float v1 = half ? acc[mi][nj].w : acc[mi][nj].y;
                    v0 = fmaxf(v0 + bias[bn + col], 0.0f);
                    v1 = fmaxf(v1 + bias[bn + col + 1], 0.0f);
                    __half h0, l0, h1, l1;
                    f16_split(v0, h0, l0);
                    f16_split(v1, h1, l1);
                    const int cell = mloc * EPI_PITCH + (col >> 1);
                    stage[cell]            = __halves2half2(h0, h1);
                    stage[EPI_PART + cell] = __halves2half2(l0, l1);
                }
            }
        }
        __syncthreads();
        // coalesced output: each row = 64 half2 = 16 uint4; 128 rows x 16 = 2048
        #pragma unroll
        for (int it = 0; it < 8; ++it) {
            int idx = tid + it * 256;
            int rw = idx >> 4, cu = idx & 15;
            int m = bm + rw;
            if (m >= nact) continue;
            const uint4* shi = (const uint4*)(stage + rw * EPI_PITCH);
            const uint4* slo = (const uint4*)(stage + EPI_PART + rw * EPI_PITCH);
            *(uint4*)(g_h_hi + (size_t)m * NDIM + bn + cu * 8) = shi[cu];
            *(uint4*)(g_h_lo + (size_t)m * NDIM + bn + cu * 8) = slo[cu];
        }
    } else {
        #pragma unroll
        for (int mi = 0; mi < 4; ++mi) {
            #pragma unroll
            for (int half = 0; half < 2; ++half) {
                const int m = bm + wm + mi * 16 + g + half * 8;
                if (m >= nact) continue;
                const int row = g_idx[m];
                const float mk  = mask[row];
                const float uwv = g_uw[row];
                #pragma unroll
                for (int nj = 0; nj < 4; ++nj) {
                    const int col = bn + wn + nj * 8 + 2 * q;
                    float v0 = half ? acc[mi][nj].z : acc[mi][nj].x;
                    float v1 = half ? acc[mi][nj].w : acc[mi][nj].y;
                    float h0 = (v0 + bias[col])     * mk;
                    float h1 = (v1 + bias[col + 1]) * mk;
                    float* pp = out_prev + (size_t)row * NDIM + col;
                    float* sp = g_st     + (size_t)row * NDIM + col;
                    float2 pv = *(const float2*)pp;
                    pv.x += h0 * uwv;
                    pv.y += h1 * uwv;
                    *(float2*)pp = pv;
                    *(float2*)sp = make_float2(h0, h1);
                }
            }
        }
    }
}

// ---------------------------------------------------------------------------
extern "C" void kernel_launch(void* const* d_in, const int* in_sizes, int n_in,
                              void* d_out, int out_size)
{
    const float* state    = (const float*)d_in[0];
    const float* mask     = (const float*)d_in[1];
    const float* step_emb = (const float*)d_in[2];
    const float* Wp       = (const float*)d_in[3];
    const float* bp       = (const float*)d_in[4];
    const float* W1       = (const float*)d_in[5];
    const float* b1       = (const float*)d_in[6];
    const float* W2       = (const float*)d_in[7];
    const float* b2       = (const float*)d_in[8];

    float* out     = (float*)d_out;
    float* out_nup = out + (size_t)MM * DD;
    float* out_rem = out_nup + MM;

    cudaFuncSetAttribute(gemm_hmma<DD, FF, 0>,
        cudaFuncAttributeMaxDynamicSharedMemorySize, DYN_SMEM);
    cudaFuncSetAttribute(gemm_hmma<FF, DD, 1>,
        cudaFuncAttributeMaxDynamicSharedMemorySize, DYN_SMEM);

    // Weight transpose+split (independent of state)
    {
        __half *w1h, *w1l, *w2h, *w2l;
        cudaGetSymbolAddress((void**)&w1h, g_w1_hi);
        cudaGetSymbolAddress((void**)&w1l, g_w1_lo);
        cudaGetSymbolAddress((void**)&w2h, g_w2_hi);
        cudaGetSymbolAddress((void**)&w2l, g_w2_lo);
        dim3 tb(32, 8);
        wsplit_kernel<<<dim3(FF / 32, DD / 32), tb>>>(W1, w1h, w1l, DD, FF);
        wsplit_kernel<<<dim3(DD / 32, FF / 32), tb>>>(W2, w2h, w2l, FF, DD);
    }

    // Init: bulk paths via async memcpy/memset (graph-capturable, no alloc)
    {
        float* stp;
        cudaGetSymbolAddress((void**)&stp, g_st);
        cudaMemcpyAsync(stp, state, (size_t)MM * DD * sizeof(float),
                        cudaMemcpyDeviceToDevice, 0);
        cudaMemsetAsync(out, 0, (size_t)out_size * sizeof(float), 0);
        init_small_kernel<<<(MM + 255) / 256, 256>>>();
    }

    dim3 g1(FF / 128, MM / 128);   // (16, 128)
    dim3 g2(DD / 128, MM / 128);   // (4, 128)

    for (int t = 0; t < NITER; ++t) {
        ponder_kernel<<<MM / 8, 256>>>(step_emb, Wp, bp, out_nup, out_rem, t);
        gemm_hmma<DD, FF, 0><<<g1, 256, DYN_SMEM>>>(b1, nullptr, nullptr, t);
        gemm_hmma<FF, DD, 1><<<g2, 256, DYN_SMEM>>>(b2, mask, out, t);
    }
}

// round 16
// speedup vs baseline: 1.0175x; 1.0128x over previous
#include <cuda_runtime.h>
#include <cuda_fp16.h>
#include <math.h>
#include <stdint.h>

#define MM   16384
#define DD   512
#define FF   2048
#define NITER 11
#define THRESH (1.0f - 0.01f)

// SMEM tile geometry (fp16): 128 rows x (32 data + 8 pad) halves = 80B pitch
#define AP       40
#define TILE_HB  (128 * AP * 2)          // 10240 B per matrix
#define STAGE_B  (4 * TILE_HB)           // Ah, Al, Bh, Bl = 40960 B
#define NSTAGE   2
#define DYN_SMEM (NSTAGE * STAGE_B)      // 81920 B -> 2 CTAs/SM

// Epilogue staging grid: 128 rows x 68 half2 cells (64 data + 4 pad)
#define EPI_PITCH 68
#define EPI_PART  (128 * EPI_PITCH)      // half2 cells per part
#define SDOT_OFF  (2 * EPI_PART * 4)     // byte offset of sdot region (69632)

// Device scratch
__device__ float  g_st[(size_t)MM * DD];       // fp32 carried state
__device__ __half g_s_hi[(size_t)MM * DD];     // split s, ORIGINAL row index
__device__ __half g_s_lo[(size_t)MM * DD];
__device__ __half g_h_hi[(size_t)MM * FF];     // compact split hidden
__device__ __half g_h_lo[(size_t)MM * FF];
__device__ __half g_w1_hi[(size_t)FF * DD];    // W1^T [F][D]
__device__ __half g_w1_lo[(size_t)FF * DD];
__device__ __half g_w2_hi[(size_t)DD * FF];    // W2^T [D][F]
__device__ __half g_w2_lo[(size_t)DD * FF];
__device__ float  g_hp[MM];
__device__ float  g_uw[MM];
__device__ int    g_idx[MM];
__device__ float  g_dotp[4][MM];               // per-N-quadrant h.Wp partials
__device__ float  g_demb[NITER];               // emb[t].Wp
__device__ int    g_nact[NITER + 1];
__device__ int    g_flag[NITER + 1];

// ---------------------------------------------------------------------------
__device__ __forceinline__ void cp_async16_s(uint32_t dst, const void* src) {
    asm volatile("cp.async.cg.shared.global [%0], [%1], 16;\n" :: "r"(dst), "l"(src));
}
template<int N> __device__ __forceinline__ void cp_wait() {
    asm volatile("cp.async.wait_group %0;\n" :: "n"(N) : "memory");
}

__device__ __forceinline__ void f16_split(float v, __half& hi, __half& lo) {
    hi = __float2half_rn(v);
    lo = __float2half_rn(v - __half2float(hi));
}

__device__ __forceinline__ void ldsm_x4(uint32_t& r0, uint32_t& r1,
                                        uint32_t& r2, uint32_t& r3, uint32_t a) {
    asm volatile("ldmatrix.sync.aligned.m8n8.x4.shared.b16 {%0,%1,%2,%3}, [%4];"
                 : "=r"(r0), "=r"(r1), "=r"(r2), "=r"(r3) : "r"(a));
}

__device__ __forceinline__ void mma_f16(float4& d,
    uint32_t a0, uint32_t a1, uint32_t a2, uint32_t a3,
    uint32_t b0, uint32_t b1) {
    asm volatile(
        "mma.sync.aligned.m16n8k16.row.col.f32.f16.f16.f32 "
        "{%0,%1,%2,%3}, {%4,%5,%6,%7}, {%8,%9}, {%0,%1,%2,%3};"
        : "+f"(d.x), "+f"(d.y), "+f"(d.z), "+f"(d.w)
        : "r"(a0), "r"(a1), "r"(a2), "r"(a3), "r"(b0), "r"(b1));
}

// ---------------------------------------------------------------------------
__global__ void init_small_kernel()
{
    int i = blockIdx.x * blockDim.x + threadIdx.x;
    if (i < MM) { g_hp[i] = 0.0f; g_idx[i] = i; }
    if (i <= NITER) { g_flag[i] = (i == 0) ? 1 : 0; g_nact[i] = 0; }
}

// emb[t].Wp table (one warp per t, fixed-order reduction -> deterministic)
__global__ void demb_kernel(const float* __restrict__ step_emb,
                            const float* __restrict__ Wp)
{
    int t = blockIdx.x;
    int lane = threadIdx.x;
    float s = 0.0f;
    #pragma unroll
    for (int i = lane; i < DD; i += 32)
        s += step_emb[(size_t)t * DD + i] * Wp[i];
    #pragma unroll
    for (int o = 16; o; o >>= 1) s += __shfl_xor_sync(0xffffffffu, s, o);
    if (lane == 0) g_demb[t] = s;
}

// Coalesced transpose + split: W[K][N] -> Th/Tl [N][K] via 32x32 smem tile
__global__ void wsplit_kernel(const float* __restrict__ W,
                              __half* __restrict__ Th, __half* __restrict__ Tl,
                              int K, int N)
{
    __shared__ float tile[32][33];
    const int bx = blockIdx.x;
    const int by = blockIdx.y;
    const int x = threadIdx.x;
    const int y = threadIdx.y;
    #pragma unroll
    for (int j = 0; j < 4; ++j)
        tile[y + j * 8][x] = W[(size_t)(by * 32 + y + j * 8) * N + bx * 32 + x];
    __syncthreads();
    #pragma unroll
    for (int j = 0; j < 4; ++j) {
        float v = tile[x][y + j * 8];
        __half hi, lo;
        f16_split(v, hi, lo);
        size_t o = (size_t)(bx * 32 + y + j * 8) * K + by * 32 + x;
        Th[o] = hi;
        Tl[o] = lo;
    }
}

// ---------------------------------------------------------------------------
// Ponder for t=0 only: full dot from state (bit-identical champion math),
// writes fp16 split of s at ORIGINAL row index.
// ---------------------------------------------------------------------------
__global__ void ponder0_kernel(const float* __restrict__ step_emb,
                               const float* __restrict__ Wp,
                               const float* __restrict__ bp,
                               float* __restrict__ out_nup,
                               float* __restrict__ out_rem)
{
    int row  = blockIdx.x * 8 + (threadIdx.x >> 5);
    int lane = threadIdx.x & 31;

    const float4* st4 = (const float4*)(g_st + (size_t)row * DD);
    const float4* e4  = (const float4*)step_emb;          // t = 0
    const float4* w4  = (const float4*)Wp;

    float4 sld[4], eld[4], wld[4];
    #pragma unroll
    for (int j = 0; j < 4; ++j) {
        int i = lane + j * 32;
        sld[j] = st4[i];
        eld[j] = e4[i];
        wld[j] = w4[i];
    }

    float4 sv[4];
    float dot = 0.0f;
    #pragma unroll
    for (int j = 0; j < 4; ++j) {
        sv[j].x = sld[j].x + eld[j].x; sv[j].y = sld[j].y + eld[j].y;
        sv[j].z = sld[j].z + eld[j].z; sv[j].w = sld[j].w + eld[j].w;
        dot += sv[j].x * wld[j].x + sv[j].y * wld[j].y
             + sv[j].z * wld[j].z + sv[j].w * wld[j].w;
    }
    #pragma unroll
    for (int o = 16; o; o >>= 1) dot += __shfl_xor_sync(0xffffffffu, dot, o);

    if (lane == 0) {
        float hp = 0.0f;
        float p = 1.0f / (1.0f + expf(-(dot + bp[0])));
        float q  = hp + p;
        float nh = (q >  THRESH) ? 1.0f : 0.0f;
        float st = (q <= THRESH) ? 1.0f : 0.0f;
        hp = hp + p * st;
        float rem = nh * (1.0f - hp);
        hp = hp + nh * rem;
        out_nup[row] = 1.0f;
        g_hp[row]    = hp;
        out_rem[row] = rem;
        g_uw[row]    = p * st + nh * rem;
        int pos = atomicAdd(&g_nact[0], 1);
        g_idx[pos] = row;
        if (hp < 1.0f) atomicOr(&g_flag[1], 1);
    }

    __half2* ph = (__half2*)(g_s_hi + (size_t)row * DD);
    __half2* pl = (__half2*)(g_s_lo + (size_t)row * DD);
    #pragma unroll
    for (int j = 0; j < 4; ++j) {
        int c2 = (lane + j * 32) * 2;
        __half h0, l0, h1, l1, h2, l2, h3, l3;
        f16_split(sv[j].x, h0, l0);
        f16_split(sv[j].y, h1, l1);
        f16_split(sv[j].z, h2, l2);
        f16_split(sv[j].w, h3, l3);
        ph[c2]     = __halves2half2(h0, h1);
        ph[c2 + 1] = __halves2half2(h2, h3);
        pl[c2]     = __halves2half2(l0, l1);
        pl[c2 + 1] = __halves2half2(l2, l3);
    }
}

// ---------------------------------------------------------------------------
// Ponder for t>=1: scalar pass. dot from gemm2-produced partials (fixed-order
// sum -> deterministic) + emb.Wp table. Halting math identical.
// ---------------------------------------------------------------------------
__global__ void ponder_fast_kernel(const float* __restrict__ bp,
                                   float* __restrict__ out_nup,
                                   float* __restrict__ out_rem,
                                   int t)
{
    if (!g_flag[t]) return;
    __shared__ int s_active;
    if (threadIdx.x == 0) s_active = 0;
    __syncthreads();

    int row = blockIdx.x * 256 + threadIdx.x;
    float hp = g_hp[row];
    if (hp < 1.0f) {
        float dot = ((g_dotp[0][row] + g_dotp[1][row])
                   + g_dotp[2][row]) + g_dotp[3][row];
        dot += g_demb[t];
        float p = 1.0f / (1.0f + expf(-(dot + bp[0])));
        float q  = hp + p;
        float nh = (q >  THRESH) ? 1.0f : 0.0f;
        float st = (q <= THRESH) ? 1.0f : 0.0f;
        hp = hp + p * st;
        float rem = out_rem[row] + nh * (1.0f - hp);
        hp = hp + nh * rem;
        out_nup[row] += 1.0f;
        g_hp[row]    = hp;
        out_rem[row] = rem;
        g_uw[row]    = p * st + nh * rem;
        int pos = atomicAdd(&g_nact[t], 1);
        g_idx[pos] = row;
        if (hp < 1.0f) atomicOr(&s_active, 1);
    }
    __syncthreads();
    if (threadIdx.x == 0 && s_active) atomicOr(&g_flag[t + 1], 1);
}

// ---------------------------------------------------------------------------
// HMMA fp16-split GEMM: 128x128 CTA, 8 warps x 64x32 warp tiles, BK=32,
// 2-stage cp.async, 2 CTAs/SM.
// MODE 0: g_h = relu(s @ W1' + b1); A rows INDIRECT via g_idx; staged epilogue
// MODE 1: h = g_h @ W2' + b2 (masked); out_prev+=h*uw; g_st=h; ALSO produces
//         next step's s-splits (staged, coalesced) and h.Wp dot partials.
// ---------------------------------------------------------------------------
template<int KDIM, int NDIM, int MODE>
__global__ __launch_bounds__(256, 2) void gemm_hmma(
    const float* __restrict__ bias,
    const float* __restrict__ mask,
    float* __restrict__ out_prev,
    const float* __restrict__ step_emb,
    const float* __restrict__ Wp,
    int t)
{
    const int nact = g_nact[t];
    const int bm = blockIdx.y * 128;
    if (bm >= nact) return;
    const int bn = blockIdx.x * 128;

    extern __shared__ unsigned char smem_raw[];
    uint32_t sb;
    asm("{ .reg .u64 tt; cvta.to.shared.u64 tt, %1; cvt.u32.u64 %0, tt; }"
        : "=r"(sb) : "l"(smem_raw));

    const int tid = threadIdx.x;
    const int tl = tid >> 6;
    const int u = tid & 63;
    const uint32_t tile_off = (uint32_t)tl * TILE_HB;

    // ---- loader base pointers; MODE 0 A-tiles are indirect via g_idx ----
    const bool indA = (MODE == 0) && (tl < 2);
    int aridx[8];
    if (indA) {
        #pragma unroll
        for (int j = 0; j < 8; ++j)
            aridx[j] = g_idx[bm + (u >> 2) + j * 16];
    }
    const __half* tpb;
    if (MODE == 0) {
        tpb = (tl == 0) ? g_s_hi
            : (tl == 1) ? g_s_lo
            : (tl == 2) ? g_w1_hi + (size_t)bn * KDIM
                        : g_w1_lo + (size_t)bn * KDIM;
    } else {
        tpb = (tl == 0) ? g_h_hi + (size_t)bm * KDIM
            : (tl == 1) ? g_h_lo + (size_t)bm * KDIM
            : (tl == 2) ? g_w2_hi + (size_t)bn * KDIM
                        : g_w2_lo + (size_t)bn * KDIM;
    }

    #define LOAD_STAGE(slot, k0)                                               \
        do {                                                                   \
            uint32_t dst_ = sb + (uint32_t)(slot) * STAGE_B + tile_off;        \
            _Pragma("unroll")                                                  \
            for (int j_ = 0; j_ < 8; ++j_) {                                   \
                int row_ = (u >> 2) + j_ * 16;                                 \
                int c_ = u & 3;                                                \
                size_t roff_ = indA ? (size_t)aridx[j_] : (size_t)row_;        \
                cp_async16_s(dst_ + (uint32_t)(row_ * (AP * 2) + c_ * 16),     \
                             tpb + roff_ * KDIM + (k0) + c_ * 8);              \
            }                                                                  \
            asm volatile("cp.async.commit_group;" ::: "memory");               \
        } while (0)

    constexpr int KT = KDIM / 32;
    LOAD_STAGE(0, 0);
    cp_wait<0>();
    __syncthreads();

    // ---- warp tiling: 8 warps, 64x32 each (2x4 warp grid) ----
    const int lane = tid & 31;
    const int w    = tid >> 5;
    const int wm   = (w >> 2) * 64;
    const int wn   = (w & 3) * 32;
    const int lr   = lane & 15;
    const int lc   = (lane >> 4) * 8;

    float4 acc[4][4];
    #pragma unroll
    for (int i = 0; i < 4; ++i)
        #pragma unroll
        for (int j = 0; j < 4; ++j)
            acc[i][j] = make_float4(0.f, 0.f, 0.f, 0.f);

    #pragma unroll 1
    for (int kt = 0; kt < KT; ++kt) {
        if (kt + 1 < KT) LOAD_STAGE((kt + 1) & 1, (kt + 1) * 32);
        const uint32_t stg = sb + (uint32_t)(kt & 1) * STAGE_B;

        #pragma unroll
        for (int sub = 0; sub < 2; ++sub) {
            const int k0 = sub * 16;
            uint32_t bh[4][2], bl[4][2];
            #pragma unroll
            for (int njp = 0; njp < 2; ++njp) {
                uint32_t addr = stg + 2 * TILE_HB
                    + (uint32_t)(((wn + njp * 16 + lr) * AP + k0 + lc) * 2);
                uint32_t r0, r1, r2, r3;
                ldsm_x4(r0, r1, r2, r3, addr);
                bh[njp * 2][0] = r0; bh[njp * 2][1] = r2;
                bh[njp * 2 + 1][0] = r1; bh[njp * 2 + 1][1] = r3;
                addr += TILE_HB;
                ldsm_x4(r0, r1, r2, r3, addr);
                bl[njp * 2][0] = r0; bl[njp * 2][1] = r2;
                bl[njp * 2 + 1][0] = r1; bl[njp * 2 + 1][1] = r3;
            }
            #pragma unroll
            for (int mi = 0; mi < 4; ++mi) {
                uint32_t addr = stg
                    + (uint32_t)(((wm + mi * 16 + lr) * AP + k0 + lc) * 2);
                uint32_t ah0, ah1, ah2, ah3, al0, al1, al2, al3;
                ldsm_x4(ah0, ah1, ah2, ah3, addr);
                ldsm_x4(al0, al1, al2, al3, addr + TILE_HB);
                #pragma unroll
                for (int nj = 0; nj < 4; ++nj) {
                    mma_f16(acc[mi][nj], ah0, ah1, ah2, ah3, bh[nj][0], bh[nj][1]);
                    mma_f16(acc[mi][nj], ah0, ah1, ah2, ah3, bl[nj][0], bl[nj][1]);
                    mma_f16(acc[mi][nj], al0, al1, al2, al3, bh[nj][0], bh[nj][1]);
                }
            }
        }

        if (kt + 1 < KT) {
            cp_wait<0>();
            __syncthreads();
        }
    }
    #undef LOAD_STAGE

    const int g = lane >> 2;
    const int q = lane & 3;

    if (MODE == 0) {
        // ---- staged epilogue: acc -> smem (hi, lo) -> coalesced ----
        __syncthreads();
        __half2* stage = (__half2*)smem_raw;
        #pragma unroll
        for (int mi = 0; mi < 4; ++mi) {
            #pragma unroll
            for (int half = 0; half < 2; ++half) {
                const int mloc = wm + mi * 16 + g + half * 8;
                #pragma unroll
                for (int nj = 0; nj < 4; ++nj) {
                    const int col = wn + nj * 8 + 2 * q;
                    float v0 = half ? acc[mi][nj].z : acc[mi][nj].x;
                    float v1 = half ? acc[mi][nj].w : acc[mi][nj].y;
                    v0 = fmaxf(v0 + bias[bn + col], 0.0f);
                    v1 = fmaxf(v1 + bias[bn + col + 1], 0.0f);
                    __half h0, l0, h1, l1;
                    f16_split(v0, h0, l0);
                    f16_split(v1, h1, l1);
                    const int cell = mloc * EPI_PITCH + (col >> 1);
                    stage[cell]            = __halves2half2(h0, h1);
                    stage[EPI_PART + cell] = __halves2half2(l0, l1);
                }
            }
        }
        __syncthreads();
        #pragma unroll
        for (int it = 0; it < 8; ++it) {
            int idx = tid + it * 256;
            int rw = idx >> 4, cu = idx & 15;
            int m = bm + rw;
            if (m >= nact) continue;
            const uint4* shi = (const uint4*)(stage + rw * EPI_PITCH);
            const uint4* slo = (const uint4*)(stage + EPI_PART + rw * EPI_PITCH);
            *(uint4*)(g_h_hi + (size_t)m * NDIM + bn + cu * 8) = shi[cu];
            *(uint4*)(g_h_lo + (size_t)m * NDIM + bn + cu * 8) = slo[cu];
        }
    } else if (t + 1 < NITER) {
        // ---- fused epilogue: h outputs + next-step s-splits + dot partials ----
        __syncthreads();                       // stages free for reuse
        __half2* stage = (__half2*)smem_raw;
        float*   sdot  = (float*)(smem_raw + SDOT_OFF);  // [128][4]
        const float* embp = step_emb + (size_t)(t + 1) * NDIM;
        const int wq = w & 3;

        #pragma unroll
        for (int mi = 0; mi < 4; ++mi) {
            #pragma unroll
            for (int half = 0; half < 2; ++half) {
                const int mloc = wm + mi * 16 + g + half * 8;
                const int m = bm + mloc;
                const bool valid = (m < nact);
                const int row = valid ? g_idx[m] : 0;
                const float mk  = valid ? mask[row] : 0.0f;
                const float uwv = valid ? g_uw[row] : 0.0f;
                float part = 0.0f;
                #pragma unroll
                for (int nj = 0; nj < 4; ++nj) {
                    const int colL = wn + nj * 8 + 2 * q;
                    const int col = bn + colL;
                    float v0 = half ? acc[mi][nj].z : acc[mi][nj].x;
                    float v1 = half ? acc[mi][nj].w : acc[mi][nj].y;
                    float h0 = (v0 + bias[col])     * mk;
                    float h1 = (v1 + bias[col + 1]) * mk;
                    if (valid) {
                        float* pp = out_prev + (size_t)row * NDIM + col;
                        float* sp = g_st     + (size_t)row * NDIM + col;
                        float2 pv = *(const float2*)pp;
                        pv.x += h0 * uwv;
                        pv.y += h1 * uwv;
                        *(float2*)pp = pv;
                        *(float2*)sp = make_float2(h0, h1);
                    }
                    part += h0 * Wp[col] + h1 * Wp[col + 1];
                    float s0 = h0 + embp[col];
                    float s1 = h1 + embp[col + 1];
                    __half a0, b0, a1, b1;
                    f16_split(s0, a0, b0);
                    f16_split(s1, a1, b1);
                    const int cell = mloc * EPI_PITCH + (colL >> 1);
                    stage[cell]            = __halves2half2(a0, a1);
                    stage[EPI_PART + cell] = __halves2half2(b0, b1);
                }
                part += __shfl_xor_sync(0xffffffffu, part, 1);
                part += __shfl_xor_sync(0xffffffffu, part, 2);
                if (q == 0) sdot[mloc * 4 + wq] = part;
            }
        }
        __syncthreads();
        if (tid < 128) {
            int m = bm + tid;
            if (m < nact) {
                float tot = ((sdot[tid * 4 + 0] + sdot[tid * 4 + 1])
                           + sdot[tid * 4 + 2]) + sdot[tid * 4 + 3];
                g_dotp[blockIdx.x][g_idx[m]] = tot;
            }
        }
        #pragma unroll
        for (int it = 0; it < 8; ++it) {
            int idx = tid + it * 256;
            int rw = idx >> 4, cu = idx & 15;
            int m = bm + rw;
            if (m >= nact) continue;
            int row = g_idx[m];
            const uint4* shi = (const uint4*)(stage + rw * EPI_PITCH);
            const uint4* slo = (const uint4*)(stage + EPI_PART + rw * EPI_PITCH);
            *(uint4*)(g_s_hi + (size_t)row * NDIM + bn + cu * 8) = shi[cu];
            *(uint4*)(g_s_lo + (size_t)row * NDIM + bn + cu * 8) = slo[cu];
        }
    } else {
        // ---- last iteration: plain epilogue ----
        #pragma unroll
        for (int mi = 0; mi < 4; ++mi) {
            #pragma unroll
            for (int half = 0; half < 2; ++half) {
                const int m = bm + wm + mi * 16 + g + half * 8;
                if (m >= nact) continue;
                const int row = g_idx[m];
                const float mk  = mask[row];
                const float uwv = g_uw[row];
                #pragma unroll
                for (int nj = 0; nj < 4; ++nj) {
                    const int col = bn + wn + nj * 8 + 2 * q;
                    float v0 = half ? acc[mi][nj].z : acc[mi][nj].x;
                    float v1 = half ? acc[mi][nj].w : acc[mi][nj].y;
                    float h0 = (v0 + bias[col])     * mk;
                    float h1 = (v1 + bias[col + 1]) * mk;
                    float* pp = out_prev + (size_t)row * NDIM + col;
                    float* sp = g_st     + (size_t)row * NDIM + col;
                    float2 pv = *(const float2*)pp;
                    pv.x += h0 * uwv;
                    pv.y += h1 * uwv;
                    *(float2*)pp = pv;
                    *(float2*)sp = make_float2(h0, h1);
                }
            }
        }
    }
}

// ---------------------------------------------------------------------------
extern "C" void kernel_launch(void* const* d_in, const int* in_sizes, int n_in,
                              void* d_out, int out_size)
{
    const float* state    = (const float*)d_in[0];
    const float* mask     = (const float*)d_in[1];
    const float* step_emb = (const float*)d_in[2];
    const float* Wp       = (const float*)d_in[3];
    const float* bp       = (const float*)d_in[4];
    const float* W1       = (const float*)d_in[5];
    const float* b1       = (const float*)d_in[6];
    const float* W2       = (const float*)d_in[7];
    const float* b2       = (const float*)d_in[8];

    float* out     = (float*)d_out;
    float* out_nup = out + (size_t)MM * DD;
    float* out_rem = out_nup + MM;

    cudaFuncSetAttribute(gemm_hmma<DD, FF, 0>,
        cudaFuncAttributeMaxDynamicSharedMemorySize, DYN_SMEM);
    cudaFuncSetAttribute(gemm_hmma<FF, DD, 1>,
        cudaFuncAttributeMaxDynamicSharedMemorySize, DYN_SMEM);

    // Weight transpose+split + emb.Wp table (independent of state)
    {
        __half *w1h, *w1l, *w2h, *w2l;
        cudaGetSymbolAddress((void**)&w1h, g_w1_hi);
        cudaGetSymbolAddress((void**)&w1l, g_w1_lo);
        cudaGetSymbolAddress((void**)&w2h, g_w2_hi);
        cudaGetSymbolAddress((void**)&w2l, g_w2_lo);
        dim3 tb(32, 8);
        wsplit_kernel<<<dim3(FF / 32, DD / 32), tb>>>(W1, w1h, w1l, DD, FF);
        wsplit_kernel<<<dim3(DD / 32, FF / 32), tb>>>(W2, w2h, w2l, FF, DD);
        demb_kernel<<<NITER, 32>>>(step_emb, Wp);
    }

    // Init: bulk paths via async memcpy/memset
    {
        float* stp;
        cudaGetSymbolAddress((void**)&stp, g_st);
        cudaMemcpyAsync(stp, state, (size_t)MM * DD * sizeof(float),
                        cudaMemcpyDeviceToDevice, 0);
        cudaMemsetAsync(out, 0, (size_t)out_size * sizeof(float), 0);
        init_small_kernel<<<(MM + 255) / 256, 256>>>();
    }

    ponder0_kernel<<<MM / 8, 256>>>(step_emb, Wp, bp, out_nup, out_rem);

    dim3 g1(FF / 128, MM / 128);   // (16, 128)
    dim3 g2(DD / 128, MM / 128);   // (4, 128)

    for (int t = 0; t < NITER; ++t) {
        if (t > 0)
            ponder_fast_kernel<<<MM / 256, 256>>>(bp, out_nup, out_rem, t);
        gemm_hmma<DD, FF, 0><<<g1, 256, DYN_SMEM>>>(
            b1, nullptr, nullptr, step_emb, Wp, t);
        gemm_hmma<FF, DD, 1><<<g2, 256, DYN_SMEM>>>(
            b2, mask, out, step_emb, Wp, t);
    }
}

// round 17
// speedup vs baseline: 1.0185x; 1.0010x over previous
#include <cuda_runtime.h>
#include <cuda_fp16.h>
#include <math.h>
#include <stdint.h>

#define MM   16384
#define DD   512
#define FF   2048
#define NITER 11
#define THRESH (1.0f - 0.01f)

// SMEM tile geometry (fp16): 128 rows x (32 data + 8 pad) halves = 80B pitch
#define AP       40
#define TILE_HB  (128 * AP * 2)          // 10240 B per matrix
#define STAGE_B  (4 * TILE_HB)           // Ah, Al, Bh, Bl = 40960 B
#define NSTAGE   2
#define DYN_SMEM (NSTAGE * STAGE_B)      // 81920 B -> 2 CTAs/SM

// Epilogue staging grid: 128 rows x 68 half2 cells (64 data + 4 pad)
#define EPI_PITCH 68
#define EPI_PART  (128 * EPI_PITCH)      // half2 cells per part
#define SDOT_OFF  (2 * EPI_PART * 4)     // byte offset of sdot region (69632)

// Device scratch
__device__ float  g_st[(size_t)MM * DD];       // fp32 carried state
__device__ __half g_s_hi[(size_t)MM * DD];     // split s, ORIGINAL row index
__device__ __half g_s_lo[(size_t)MM * DD];
__device__ __half g_h_hi[(size_t)MM * FF];     // compact split hidden
__device__ __half g_h_lo[(size_t)MM * FF];
__device__ __half g_w1_hi[(size_t)FF * DD];    // W1^T [F][D]
__device__ __half g_w1_lo[(size_t)FF * DD];
__device__ __half g_w2_hi[(size_t)DD * FF];    // W2^T [D][F]
__device__ __half g_w2_lo[(size_t)DD * FF];
__device__ float  g_hp[MM];
__device__ float  g_uw[2][MM];                 // parity double-buffered
__device__ int    g_idx[2][MM];                // parity double-buffered
__device__ float  g_dotp[4][MM];               // per-N-quadrant h.Wp partials
__device__ float  g_demb[NITER];               // emb[t].Wp
__device__ int    g_nact[NITER + 1];
__device__ int    g_cnt[NITER][128];           // gemm2 rowblock arrival counters

// ---------------------------------------------------------------------------
__device__ __forceinline__ void cp_async16_s(uint32_t dst, const void* src) {
    asm volatile("cp.async.cg.shared.global [%0], [%1], 16;\n" :: "r"(dst), "l"(src));
}
template<int N> __device__ __forceinline__ void cp_wait() {
    asm volatile("cp.async.wait_group %0;\n" :: "n"(N) : "memory");
}

__device__ __forceinline__ void f16_split(float v, __half& hi, __half& lo) {
    hi = __float2half_rn(v);
    lo = __float2half_rn(v - __half2float(hi));
}

__device__ __forceinline__ void ldsm_x4(uint32_t& r0, uint32_t& r1,
                                        uint32_t& r2, uint32_t& r3, uint32_t a) {
    asm volatile("ldmatrix.sync.aligned.m8n8.x4.shared.b16 {%0,%1,%2,%3}, [%4];"
                 : "=r"(r0), "=r"(r1), "=r"(r2), "=r"(r3) : "r"(a));
}

__device__ __forceinline__ void mma_f16(float4& d,
    uint32_t a0, uint32_t a1, uint32_t a2, uint32_t a3,
    uint32_t b0, uint32_t b1) {
    asm volatile(
        "mma.sync.aligned.m16n8k16.row.col.f32.f16.f16.f32 "
        "{%0,%1,%2,%3}, {%4,%5,%6,%7}, {%8,%9}, {%0,%1,%2,%3};"
        : "+f"(d.x), "+f"(d.y), "+f"(d.z), "+f"(d.w)
        : "r"(a0), "r"(a1), "r"(a2), "r"(a3), "r"(b0), "r"(b1));
}

// ---------------------------------------------------------------------------
__global__ void init_small_kernel()
{
    int i = blockIdx.x * blockDim.x + threadIdx.x;
    if (i < MM) { g_hp[i] = 0.0f; g_idx[0][i] = i; g_idx[1][i] = i; }
    if (i <= NITER) g_nact[i] = 0;
    if (i < NITER * 128) (&g_cnt[0][0])[i] = 0;
}

// emb[t].Wp table (one warp per t, fixed-order reduction -> deterministic)
__global__ void demb_kernel(const float* __restrict__ step_emb,
                            const float* __restrict__ Wp)
{
    int t = blockIdx.x;
    int lane = threadIdx.x;
    float s = 0.0f;
    #pragma unroll
    for (int i = lane; i < DD; i += 32)
        s += step_emb[(size_t)t * DD + i] * Wp[i];
    #pragma unroll
    for (int o = 16; o; o >>= 1) s += __shfl_xor_sync(0xffffffffu, s, o);
    if (lane == 0) g_demb[t] = s;
}

// Coalesced transpose + split: W[K][N] -> Th/Tl [N][K] via 32x32 smem tile
__global__ void wsplit_kernel(const float* __restrict__ W,
                              __half* __restrict__ Th, __half* __restrict__ Tl,
                              int K, int N)
{
    __shared__ float tile[32][33];
    const int bx = blockIdx.x;
    const int by = blockIdx.y;
    const int x = threadIdx.x;
    const int y = threadIdx.y;
    #pragma unroll
    for (int j = 0; j < 4; ++j)
        tile[y + j * 8][x] = W[(size_t)(by * 32 + y + j * 8) * N + bx * 32 + x];
    __syncthreads();
    #pragma unroll
    for (int j = 0; j < 4; ++j) {
        float v = tile[x][y + j * 8];
        __half hi, lo;
        f16_split(v, hi, lo);
        size_t o = (size_t)(bx * 32 + y + j * 8) * K + by * 32 + x;
        Th[o] = hi;
        Tl[o] = lo;
    }
}

// ---------------------------------------------------------------------------
// Ponder for t=0 only: full dot from state (bit-identical champion math),
// writes fp16 split of s at ORIGINAL row index, parity buffer 0.
// ---------------------------------------------------------------------------
__global__ void ponder0_kernel(const float* __restrict__ step_emb,
                               const float* __restrict__ Wp,
                               const float* __restrict__ bp,
                               float* __restrict__ out_nup,
                               float* __restrict__ out_rem)
{
    int row  = blockIdx.x * 8 + (threadIdx.x >> 5);
    int lane = threadIdx.x & 31;

    const float4* st4 = (const float4*)(g_st + (size_t)row * DD);
    const float4* e4  = (const float4*)step_emb;          // t = 0
    const float4* w4  = (const float4*)Wp;

    float4 sld[4], eld[4], wld[4];
    #pragma unroll
    for (int j = 0; j < 4; ++j) {
        int i = lane + j * 32;
        sld[j] = st4[i];
        eld[j] = e4[i];
        wld[j] = w4[i];
    }

    float4 sv[4];
    float dot = 0.0f;
    #pragma unroll
    for (int j = 0; j < 4; ++j) {
        sv[j].x = sld[j].x + eld[j].x; sv[j].y = sld[j].y + eld[j].y;
        sv[j].z = sld[j].z + eld[j].z; sv[j].w = sld[j].w + eld[j].w;
        dot += sv[j].x * wld[j].x + sv[j].y * wld[j].y
             + sv[j].z * wld[j].z + sv[j].w * wld[j].w;
    }
    #pragma unroll
    for (int o = 16; o; o >>= 1) dot += __shfl_xor_sync(0xffffffffu, dot, o);

    if (lane == 0) {
        float hp = 0.0f;
        float p = 1.0f / (1.0f + expf(-(dot + bp[0])));
        float q  = hp + p;
        float nh = (q >  THRESH) ? 1.0f : 0.0f;
        float st = (q <= THRESH) ? 1.0f : 0.0f;
        hp = hp + p * st;
        float rem = nh * (1.0f - hp);
        hp = hp + nh * rem;
        out_nup[row] = 1.0f;
        g_hp[row]    = hp;
        out_rem[row] = rem;
        g_uw[0][row] = p * st + nh * rem;
        int pos = atomicAdd(&g_nact[0], 1);
        g_idx[0][pos] = row;
    }

    __half2* ph = (__half2*)(g_s_hi + (size_t)row * DD);
    __half2* pl = (__half2*)(g_s_lo + (size_t)row * DD);
    #pragma unroll
    for (int j = 0; j < 4; ++j) {
        int c2 = (lane + j * 32) * 2;
        __half h0, l0, h1, l1, h2, l2, h3, l3;
        f16_split(sv[j].x, h0, l0);
        f16_split(sv[j].y, h1, l1);
        f16_split(sv[j].z, h2, l2);
        f16_split(sv[j].w, h3, l3);
        ph[c2]     = __halves2half2(h0, h1);
        ph[c2 + 1] = __halves2half2(h2, h3);
        pl[c2]     = __halves2half2(l0, l1);
        pl[c2 + 1] = __halves2half2(l2, l3);
    }
}

// ---------------------------------------------------------------------------
// HMMA fp16-split GEMM: 128x128 CTA, 8 warps x 64x32 warp tiles, BK=32,
// 2-stage cp.async, 2 CTAs/SM.
// MODE 0: g_h = relu(s @ W1' + b1); A rows INDIRECT via g_idx[pb]
// MODE 1: h = g_h @ W2' + b2 (masked); out_prev+=h*uw; g_st=h; produces
//         next-step s-splits + dot partials; 4th CTA per rowblock then runs
//         the scalar ponder(t+1) into parity buffer pb^1 (race-free).
// ---------------------------------------------------------------------------
template<int KDIM, int NDIM, int MODE>
__global__ __launch_bounds__(256, 2) void gemm_hmma(
    const float* __restrict__ bias,
    const float* __restrict__ mask,
    float* __restrict__ out_prev,
    const float* __restrict__ step_emb,
    const float* __restrict__ Wp,
    const float* __restrict__ bp,
    float* __restrict__ out_nup,
    float* __restrict__ out_rem,
    int t)
{
    const int nact = g_nact[t];
    const int bm = blockIdx.y * 128;
    if (bm >= nact) return;
    const int bn = blockIdx.x * 128;
    const int pb = t & 1;

    extern __shared__ unsigned char smem_raw[];
    uint32_t sb;
    asm("{ .reg .u64 tt; cvta.to.shared.u64 tt, %1; cvt.u32.u64 %0, tt; }"
        : "=r"(sb) : "l"(smem_raw));

    const int tid = threadIdx.x;
    const int tl = tid >> 6;
    const int u = tid & 63;
    const uint32_t tile_off = (uint32_t)tl * TILE_HB;

    // ---- loader base pointers; MODE 0 A-tiles are indirect via g_idx ----
    const bool indA = (MODE == 0) && (tl < 2);
    int aridx[8];
    if (indA) {
        #pragma unroll
        for (int j = 0; j < 8; ++j)
            aridx[j] = g_idx[pb][bm + (u >> 2) + j * 16];
    }
    const __half* tpb;
    if (MODE == 0) {
        tpb = (tl == 0) ? g_s_hi
            : (tl == 1) ? g_s_lo
            : (tl == 2) ? g_w1_hi + (size_t)bn * KDIM
                        : g_w1_lo + (size_t)bn * KDIM;
    } else {
        tpb = (tl == 0) ? g_h_hi + (size_t)bm * KDIM
            : (tl == 1) ? g_h_lo + (size_t)bm * KDIM
            : (tl == 2) ? g_w2_hi + (size_t)bn * KDIM
                        : g_w2_lo + (size_t)bn * KDIM;
    }

    #define LOAD_STAGE(slot, k0)                                               \
        do {                                                                   \
            uint32_t dst_ = sb + (uint32_t)(slot) * STAGE_B + tile_off;        \
            _Pragma("unroll")                                                  \
            for (int j_ = 0; j_ < 8; ++j_) {                                   \
                int row_ = (u >> 2) + j_ * 16;                                 \
                int c_ = u & 3;                                                \
                size_t roff_ = indA ? (size_t)aridx[j_] : (size_t)row_;        \
                cp_async16_s(dst_ + (uint32_t)(row_ * (AP * 2) + c_ * 16),     \
                             tpb + roff_ * KDIM + (k0) + c_ * 8);              \
            }                                                                  \
            asm volatile("cp.async.commit_group;" ::: "memory");               \
        } while (0)

    constexpr int KT = KDIM / 32;
    LOAD_STAGE(0, 0);
    cp_wait<0>();
    __syncthreads();

    // ---- warp tiling: 8 warps, 64x32 each (2x4 warp grid) ----
    const int lane = tid & 31;
    const int w    = tid >> 5;
    const int wm   = (w >> 2) * 64;
    const int wn   = (w & 3) * 32;
    const int lr   = lane & 15;
    const int lc   = (lane >> 4) * 8;

    float4 acc[4][4];
    #pragma unroll
    for (int i = 0; i < 4; ++i)
        #pragma unroll
        for (int j = 0; j < 4; ++j)
            acc[i][j] = make_float4(0.f, 0.f, 0.f, 0.f);

    #pragma unroll 1
    for (int kt = 0; kt < KT; ++kt) {
        if (kt + 1 < KT) LOAD_STAGE((kt + 1) & 1, (kt + 1) * 32);
        const uint32_t stg = sb + (uint32_t)(kt & 1) * STAGE_B;

        #pragma unroll
        for (int sub = 0; sub < 2; ++sub) {
            const int k0 = sub * 16;
            uint32_t bh[4][2], bl[4][2];
            #pragma unroll
            for (int njp = 0; njp < 2; ++njp) {
                uint32_t addr = stg + 2 * TILE_HB
                    + (uint32_t)(((wn + njp * 16 + lr) * AP + k0 + lc) * 2);
                uint32_t r0, r1, r2, r3;
                ldsm_x4(r0, r1, r2, r3, addr);
                bh[njp * 2][0] = r0; bh[njp * 2][1] = r2;
                bh[njp * 2 + 1][0] = r1; bh[njp * 2 + 1][1] = r3;
                addr += TILE_HB;
                ldsm_x4(r0, r1, r2, r3, addr);
                bl[njp * 2][0] = r0; bl[njp * 2][1] = r2;
                bl[njp * 2 + 1][0] = r1; bl[njp * 2 + 1][1] = r3;
            }
            #pragma unroll
            for (int mi = 0; mi < 4; ++mi) {
                uint32_t addr = stg
                    + (uint32_t)(((wm + mi * 16 + lr) * AP + k0 + lc) * 2);
                uint32_t ah0, ah1, ah2, ah3, al0, al1, al2, al3;
                ldsm_x4(ah0, ah1, ah2, ah3, addr);
                ldsm_x4(al0, al1, al2, al3, addr + TILE_HB);
                #pragma unroll
                for (int nj = 0; nj < 4; ++nj) {
                    mma_f16(acc[mi][nj], ah0, ah1, ah2, ah3, bh[nj][0], bh[nj][1]);
                    mma_f16(acc[mi][nj], ah0, ah1, ah2, ah3, bl[nj][0], bl[nj][1]);
                    mma_f16(acc[mi][nj], al0, al1, al2, al3, bh[nj][0], bh[nj][1]);
                }
            }
        }

        if (kt + 1 < KT) {
            cp_wait<0>();
            __syncthreads();
        }
    }
    #undef LOAD_STAGE

    const int g = lane >> 2;
    const int q = lane & 3;

    if (MODE == 0) {
        // ---- staged epilogue: acc -> smem (hi, lo) -> coalesced ----
        __syncthreads();
        __half2* stage = (__half2*)smem_raw;
        #pragma unroll
        for (int mi = 0; mi < 4; ++mi) {
            #pragma unroll
            for (int half = 0; half < 2; ++half) {
                const int mloc = wm + mi * 16 + g + half * 8;
                #pragma unroll
                for (int nj = 0; nj < 4; ++nj) {
                    const int col = wn + nj * 8 + 2 * q;
                    float v0 = half ? acc[mi][nj].z : acc[mi][nj].x;
                    float v1 = half ? acc[mi][nj].w : acc[mi][nj].y;
                    v0 = fmaxf(v0 + bias[bn + col], 0.0f);
                    v1 = fmaxf(v1 + bias[bn + col + 1], 0.0f);
                    __half h0, l0, h1, l1;
                    f16_split(v0, h0, l0);
                    f16_split(v1, h1, l1);
                    const int cell = mloc * EPI_PITCH + (col >> 1);
                    stage[cell]            = __halves2half2(h0, h1);
                    stage[EPI_PART + cell] = __halves2half2(l0, l1);
                }
            }
        }
        __syncthreads();
        #pragma unroll
        for (int it = 0; it < 8; ++it) {
            int idx = tid + it * 256;
            int rw = idx >> 4, cu = idx & 15;
            int m = bm + rw;
            if (m >= nact) continue;
            const uint4* shi = (const uint4*)(stage + rw * EPI_PITCH);
            const uint4* slo = (const uint4*)(stage + EPI_PART + rw * EPI_PITCH);
            *(uint4*)(g_h_hi + (size_t)m * NDIM + bn + cu * 8) = shi[cu];
            *(uint4*)(g_h_lo + (size_t)m * NDIM + bn + cu * 8) = slo[cu];
        }
    } else if (t + 1 < NITER) {
        // ---- fused epilogue: h outputs + next-step s-splits + dot partials ----
        __syncthreads();
        __half2* stage = (__half2*)smem_raw;
        float*   sdot  = (float*)(smem_raw + SDOT_OFF);  // [128][4]
        const float* embp = step_emb + (size_t)(t + 1) * NDIM;
        const int wq = w & 3;

        #pragma unroll
        for (int mi = 0; mi < 4; ++mi) {
            #pragma unroll
            for (int half = 0; half < 2; ++half) {
                const int mloc = wm + mi * 16 + g + half * 8;
                const int m = bm + mloc;
                const bool valid = (m < nact);
                const int row = valid ? g_idx[pb][m] : 0;
                const float mk  = valid ? mask[row] : 0.0f;
                const float uwv = valid ? g_uw[pb][row] : 0.0f;
                float part = 0.0f;
                #pragma unroll
                for (int nj = 0; nj < 4; ++nj) {
                    const int colL = wn + nj * 8 + 2 * q;
                    const int col = bn + colL;
                    float v0 = half ? acc[mi][nj].z : acc[mi][nj].x;
                    float v1 = half ? acc[mi][nj].w : acc[mi][nj].y;
                    float h0 = (v0 + bias[col])     * mk;
                    float h1 = (v1 + bias[col + 1]) * mk;
                    if (valid) {
                        float* pp = out_prev + (size_t)row * NDIM + col;
                        float* sp = g_st     + (size_t)row * NDIM + col;
                        float2 pv = *(const float2*)pp;
                        pv.x += h0 * uwv;
                        pv.y += h1 * uwv;
                        *(float2*)pp = pv;
                        *(float2*)sp = make_float2(h0, h1);
                    }
                    part += h0 * Wp[col] + h1 * Wp[col + 1];
                    float s0 = h0 + embp[col];
                    float s1 = h1 + embp[col + 1];
                    __half a0, b0, a1, b1;
                    f16_split(s0, a0, b0);
                    f16_split(s1, a1, b1);
                    const int cell = mloc * EPI_PITCH + (colL >> 1);
                    stage[cell]            = __halves2half2(a0, a1);
                    stage[EPI_PART + cell] = __halves2half2(b0, b1);
                }
                part += __shfl_xor_sync(0xffffffffu, part, 1);
                part += __shfl_xor_sync(0xffffffffu, part, 2);
                if (q == 0) sdot[mloc * 4 + wq] = part;
            }
        }
        __syncthreads();
        if (tid < 128) {
            int m = bm + tid;
            if (m < nact) {
                float tot = ((sdot[tid * 4 + 0] + sdot[tid * 4 + 1])
                           + sdot[tid * 4 + 2]) + sdot[tid * 4 + 3];
                g_dotp[blockIdx.x][g_idx[pb][m]] = tot;
            }
        }
        #pragma unroll
        for (int it = 0; it < 8; ++it) {
            int idx = tid + it * 256;
            int rw = idx >> 4, cu = idx & 15;
            int m = bm + rw;
            if (m >= nact) continue;
            int row = g_idx[pb][m];
            const uint4* shi = (const uint4*)(stage + rw * EPI_PITCH);
            const uint4* slo = (const uint4*)(stage + EPI_PART + rw * EPI_PITCH);
            *(uint4*)(g_s_hi + (size_t)row * NDIM + bn + cu * 8) = shi[cu];
            *(uint4*)(g_s_lo + (size_t)row * NDIM + bn + cu * 8) = slo[cu];
        }

        // ---- winner CTA runs scalar ponder(t+1) (parity buffer pb^1) ----
        __syncthreads();
        __shared__ int s_win;
        if (tid == 0) {
            __threadfence();                       // release dotp/s/uw-read state
            int old = atomicAdd(&g_cnt[t][blockIdx.y], 1);
            s_win = (old == 3) ? 1 : 0;
        }
        __syncthreads();
        if (s_win) {
            if (tid == 0) __threadfence();         // acquire peers' dotp
            __syncthreads();
            if (tid < 128) {
                int m = bm + tid;
                if (m < nact) {
                    int row = g_idx[pb][m];
                    float hp = g_hp[row];
                    if (hp < 1.0f) {
                        float dot = ((g_dotp[0][row] + g_dotp[1][row])
                                   + g_dotp[2][row]) + g_dotp[3][row];
                        dot += g_demb[t + 1];
                        float p = 1.0f / (1.0f + expf(-(dot + bp[0])));
                        float qq = hp + p;
                        float nh = (qq >  THRESH) ? 1.0f : 0.0f;
                        float st = (qq <= THRESH) ? 1.0f : 0.0f;
                        hp = hp + p * st;
                        float rem = out_rem[row] + nh * (1.0f - hp);
                        hp = hp + nh * rem;
                        out_nup[row] += 1.0f;
                        g_hp[row]    = hp;
                        out_rem[row] = rem;
                        g_uw[pb ^ 1][row] = p * st + nh * rem;
                        int pos = atomicAdd(&g_nact[t + 1], 1);
                        g_idx[pb ^ 1][pos] = row;
                    }
                }
            }
        }
    } else {
        // ---- last iteration: plain epilogue ----
        #pragma unroll
        for (int mi = 0; mi < 4; ++mi) {
            #pragma unroll
            for (int half = 0; half < 2; ++half) {
                const int m = bm + wm + mi * 16 + g + half * 8;
                if (m >= nact) continue;
                const int row = g_idx[pb][m];
                const float mk  = mask[row];
                const float uwv = g_uw[pb][row];
                #pragma unroll
                for (int nj = 0; nj < 4; ++nj) {
                    const int col = bn + wn + nj * 8 + 2 * q;
                    float v0 = half ? acc[mi][nj].z : acc[mi][nj].x;
                    float v1 = half ? acc[mi][nj].w : acc[mi][nj].y;
                    float h0 = (v0 + bias[col])     * mk;
                    float h1 = (v1 + bias[col + 1]) * mk;
                    float* pp = out_prev + (size_t)row * NDIM + col;
                    float* sp = g_st     + (size_t)row * NDIM + col;
                    float2 pv = *(const float2*)pp;
                    pv.x += h0 * uwv;
                    pv.y += h1 * uwv;
                    *(float2*)pp = pv;
                    *(float2*)sp = make_float2(h0, h1);
                }
            }
        }
    }
}

// ---------------------------------------------------------------------------
extern "C" void kernel_launch(void* const* d_in, const int* in_sizes, int n_in,
                              void* d_out, int out_size)
{
    const float* state    = (const float*)d_in[0];
    const float* mask     = (const float*)d_in[1];
    const float* step_emb = (const float*)d_in[2];
    const float* Wp       = (const float*)d_in[3];
    const float* bp       = (const float*)d_in[4];
    const float* W1       = (const float*)d_in[5];
    const float* b1       = (const float*)d_in[6];
    const float* W2       = (const float*)d_in[7];
    const float* b2       = (const float*)d_in[8];

    float* out     = (float*)d_out;
    float* out_nup = out + (size_t)MM * DD;
    float* out_rem = out_nup + MM;

    cudaFuncSetAttribute(gemm_hmma<DD, FF, 0>,
        cudaFuncAttributeMaxDynamicSharedMemorySize, DYN_SMEM);
    cudaFuncSetAttribute(gemm_hmma<FF, DD, 1>,
        cudaFuncAttributeMaxDynamicSharedMemorySize, DYN_SMEM);

    // Weight transpose+split + emb.Wp table (independent of state)
    {
        __half *w1h, *w1l, *w2h, *w2l;
        cudaGetSymbolAddress((void**)&w1h, g_w1_hi);
        cudaGetSymbolAddress((void**)&w1l, g_w1_lo);
        cudaGetSymbolAddress((void**)&w2h, g_w2_hi);
        cudaGetSymbolAddress((void**)&w2l, g_w2_lo);
        dim3 tb(32, 8);
        wsplit_kernel<<<dim3(FF / 32, DD / 32), tb>>>(W1, w1h, w1l, DD, FF);
        wsplit_kernel<<<dim3(DD / 32, FF / 32), tb>>>(W2, w2h, w2l, FF, DD);
        demb_kernel<<<NITER, 32>>>(step_emb, Wp);
    }

    // Init: bulk paths via async memcpy/memset
    {
        float* stp;
        cudaGetSymbolAddress((void**)&stp, g_st);
        cudaMemcpyAsync(stp, state, (size_t)MM * DD * sizeof(float),
                        cudaMemcpyDeviceToDevice, 0);
        cudaMemsetAsync(out, 0, (size_t)out_size * sizeof(float), 0);
        init_small_kernel<<<(MM + 255) / 256, 256>>>();
    }

    ponder0_kernel<<<MM / 8, 256>>>(step_emb, Wp, bp, out_nup, out_rem);

    dim3 g1(FF / 128, MM / 128);   // (16, 128)
    dim3 g2(DD / 128, MM / 128);   // (4, 128)

    for (int t = 0; t < NITER; ++t) {
        gemm_hmma<DD, FF, 0><<<g1, 256, DYN_SMEM>>>(
            b1, nullptr, nullptr, step_emb, Wp, bp, out_nup, out_rem, t);
        gemm_hmma<FF, DD, 1><<<g2, 256, DYN_SMEM>>>(
            b2, mask, out, step_emb, Wp, bp, out_nup, out_rem, t);
    }
}